// round 6
// baseline (speedup 1.0000x reference)
#include <cuda_runtime.h>
#include <cstdint>

#define NB   8
#define CDIM 64
#define HH   256
#define WW   256
#define KK   3
#define EPSV 1e-5f
#define RPT  32   // rows per thread in conv

// scratch (allocation-free rule: device globals)
__device__ float g_gap[NB * CDIM];
__device__ float g_fH[NB * CDIM * KK];
__device__ float g_fW[NB * CDIM * KK];

// ---------------- Kernel 1: global average pool per (n,c) plane ----------------
__global__ void gap_kernel(const float* __restrict__ x) {
    int nc = blockIdx.x;                 // 0..511
    const float4* p = (const float4*)(x + (size_t)nc * HH * WW);
    float s = 0.f;
    // 16384 float4; 512 threads -> exactly 32 float4 each (full unroll, max MLP)
    #pragma unroll
    for (int j = 0; j < 32; j++) {
        float4 v = p[threadIdx.x + j * 512];
        s += (v.x + v.y) + (v.z + v.w);
    }
    __shared__ float red[512];
    red[threadIdx.x] = s;
    __syncthreads();
    for (int o = 256; o > 0; o >>= 1) {
        if (threadIdx.x < o) red[threadIdx.x] += red[threadIdx.x + o];
        __syncthreads();
    }
    if (threadIdx.x == 0)
        g_gap[nc] = red[0] * (1.0f / (HH * WW));
}

// ---------------- Kernel 2: taps = tanh(BN(gap @ w^T)) for both branches ----------------
__global__ void taps_kernel(const float* __restrict__ wH, const float* __restrict__ gH,
                            const float* __restrict__ bH, const float* __restrict__ mH,
                            const float* __restrict__ vH,
                            const float* __restrict__ wW, const float* __restrict__ gW,
                            const float* __restrict__ bW, const float* __restrict__ mW,
                            const float* __restrict__ vW) {
    int idx = blockIdx.x * blockDim.x + threadIdx.x;
    const int PER = NB * CDIM * KK;          // 1536 per branch
    if (idx >= 2 * PER) return;
    int branch = idx / PER;                  // 0 = H, 1 = W
    int r = idx - branch * PER;
    int n = r / (CDIM * KK);
    int i = r - n * (CDIM * KK);             // row of w, 0..191 (== c*K + k)

    const float* w = branch ? wW : wH;
    const float* g = branch ? gW : gH;
    const float* b = branch ? bW : bH;
    const float* m = branch ? mW : mH;
    const float* v = branch ? vW : vH;

    const float* gp = g_gap + n * CDIM;
    const float* wr = w + i * CDIM;
    float s = 0.f;
    #pragma unroll
    for (int c = 0; c < CDIM; c++) s += gp[c] * wr[c];

    float f = (s - m[i]) * (g[i] * rsqrtf(v[i] + EPSV)) + b[i];
    f = tanhf(f);
    (branch ? g_fW : g_fH)[n * CDIM * KK + i] = f;
}

// ---------------- Kernel 3: fused strip conv, rolling registers, shfl halo ----------------
// grid = 512 blocks (one per (n,c) plane), 512 threads.
// thread: g = t&63 (float4 column group), chunk = t>>6 (8 chunks of RPT=32 rows).
// Within a warp, g is consecutive (lane = g&31), so horizontal neighbors come
// from adjacent lanes via shfl; only warp-edge lanes touch memory for the halo.
__global__ void __launch_bounds__(512) conv_kernel(const float* __restrict__ x,
                                                   float* __restrict__ out) {
    int plane = blockIdx.x;              // nc, 0..511
    int n   = plane >> 6;
    int cch = plane & 63;
    int t = threadIdx.x;
    int g = t & 63;
    int lane = t & 31;
    int h0 = (t >> 6) * RPT;

    const float4* xp4 = (const float4*)(x + (size_t)plane * HH * WW);
    const float*  xp  = x + (size_t)plane * HH * WW;

    float fh0 = g_fH[plane * 3 + 0], fh1 = g_fH[plane * 3 + 1], fh2 = g_fH[plane * 3 + 2];
    float fw0 = g_fW[plane * 3 + 0], fw1 = g_fW[plane * 3 + 1], fw2 = g_fW[plane * 3 + 2];

    float4* o1 = (float4*)(out + ((size_t)n * 2 * CDIM + cch) * HH * WW);
    float4* o2 = o1 + (size_t)CDIM * HH * WW / 4;

    auto process = [&](int h, const float4& up, const float4& ce, const float4& dn) {
        // horizontal halo from neighboring lanes
        float xl = __shfl_up_sync(0xFFFFFFFFu, ce.w, 1);
        float xr = __shfl_down_sync(0xFFFFFFFFu, ce.x, 1);
        if (lane == 0)
            xl = (g == 0)  ? ce.y : xp[h * WW + 4 * g - 1];
        if (lane == 31)
            xr = (g == 63) ? ce.z : xp[h * WW + 4 * g + 4];
        float4 h4;
        h4.x = fh0 * xl   + fh1 * ce.x + fh2 * ce.y;
        h4.y = fh0 * ce.x + fh1 * ce.y + fh2 * ce.z;
        h4.z = fh0 * ce.y + fh1 * ce.z + fh2 * ce.w;
        h4.w = fh0 * ce.z + fh1 * ce.w + fh2 * xr;
        float4 v4;
        v4.x = fw0 * up.x + fw1 * ce.x + fw2 * dn.x;
        v4.y = fw0 * up.y + fw1 * ce.y + fw2 * dn.y;
        v4.z = fw0 * up.z + fw1 * ce.z + fw2 * dn.z;
        v4.w = fw0 * up.w + fw1 * ce.w + fw2 * dn.w;
        __stcs(&o1[h * (WW / 4) + g], h4);   // streaming: don't evict x from L2
        __stcs(&o2[h * (WW / 4) + g], v4);
    };

    // rolling window: u = row h-1, cc = row h
    int hu = (h0 == 0) ? 1 : h0 - 1;         // reflect top
    float4 u  = xp4[hu * (WW / 4) + g];
    float4 cc = xp4[h0 * (WW / 4) + g];

    #pragma unroll
    for (int hb = 0; hb < RPT; hb += 4) {
        int h = h0 + hb;
        int r1 = h + 1, r2 = h + 2, r3 = h + 3, r4 = h + 4;
        if (r4 > HH - 1) r4 = HH - 2;        // reflect bottom (only last batch)
        if (r3 > HH - 1) r3 = HH - 2;
        // 4 independent vector loads -> MLP 4
        float4 d0 = xp4[r1 * (WW / 4) + g];
        float4 d1 = xp4[r2 * (WW / 4) + g];
        float4 d2 = xp4[r3 * (WW / 4) + g];
        float4 d3 = xp4[r4 * (WW / 4) + g];

        process(h,     u,  cc, d0);
        process(h + 1, cc, d0, d1);
        process(h + 2, d0, d1, d2);
        process(h + 3, d1, d2, d3);

        u  = d2;
        cc = d3;
    }
}

extern "C" void kernel_launch(void* const* d_in, const int* in_sizes, int n_in,
                              void* d_out, int out_size) {
    const float* x  = (const float*)d_in[0];
    const float* wH = (const float*)d_in[1];
    const float* gH = (const float*)d_in[2];
    const float* bH = (const float*)d_in[3];
    const float* mH = (const float*)d_in[4];
    const float* vH = (const float*)d_in[5];
    const float* wW = (const float*)d_in[6];
    const float* gW = (const float*)d_in[7];
    const float* bW = (const float*)d_in[8];
    const float* mW = (const float*)d_in[9];
    const float* vW = (const float*)d_in[10];
    float* out = (float*)d_out;

    gap_kernel<<<NB * CDIM, 512>>>(x);
    taps_kernel<<<(2 * NB * CDIM * KK + 255) / 256, 256>>>(wH, gH, bH, mH, vH,
                                                           wW, gW, bW, mW, vW);
    conv_kernel<<<NB * CDIM, 512>>>(x, out);
}

// round 7
// speedup vs baseline: 1.0407x; 1.0407x over previous
#include <cuda_runtime.h>
#include <cstdint>

#define NB   8
#define CDIM 64
#define HH   256
#define WW   256
#define KK   3
#define EPSV 1e-5f
#define RPT  32   // rows per thread in conv

// scratch (allocation-free rule: device globals)
__device__ float g_gap[NB * CDIM];

// ---------------- Kernel 1: global average pool per (n,c) plane ----------------
__global__ void gap_kernel(const float* __restrict__ x) {
    int nc = blockIdx.x;                 // 0..511
    const float4* p = (const float4*)(x + (size_t)nc * HH * WW);
    float s = 0.f;
    #pragma unroll 8
    for (int i = threadIdx.x; i < (HH * WW) / 4; i += 512) {
        float4 v = p[i];
        s += (v.x + v.y) + (v.z + v.w);
    }
    __shared__ float red[512];
    red[threadIdx.x] = s;
    __syncthreads();
    for (int o = 256; o > 0; o >>= 1) {
        if (threadIdx.x < o) red[threadIdx.x] += red[threadIdx.x + o];
        __syncthreads();
    }
    if (threadIdx.x == 0)
        g_gap[nc] = red[0] * (1.0f / (HH * WW));
}

// ---------------- Kernel 2: fused taps + strip conv ----------------
// grid = 1024 blocks (2 per (n,c) plane: half=128 rows each), 256 threads.
// thread: g = t&63 (float4 column group), chunk = t>>6 (4 chunks of RPT=32 rows).
// Block prologue: threads 0..5 compute the 6 dynamic taps (BN+tanh over the
// gap-GEMV row) and broadcast via smem.
__global__ void __launch_bounds__(256) conv_kernel(
        const float* __restrict__ x, float* __restrict__ out,
        const float* __restrict__ wH, const float* __restrict__ gH,
        const float* __restrict__ bH, const float* __restrict__ mH,
        const float* __restrict__ vH,
        const float* __restrict__ wW, const float* __restrict__ gW,
        const float* __restrict__ bW, const float* __restrict__ mW,
        const float* __restrict__ vW) {
    int plane = blockIdx.x >> 1;         // nc, 0..511
    int half  = blockIdx.x & 1;
    int n   = plane >> 6;
    int cch = plane & 63;
    int t = threadIdx.x;
    int g = t & 63;
    int h0 = half * 128 + (t >> 6) * RPT;

    __shared__ float taps[6];            // [0..2]=H, [3..5]=W
    if (t < 6) {
        int branch = t / 3;              // 0=H, 1=W
        int k = t - branch * 3;
        int row = cch * 3 + k;
        const float* w = branch ? wW : wH;
        const float* gg = branch ? gW : gH;
        const float* bb = branch ? bW : bH;
        const float* mm = branch ? mW : mH;
        const float* vv = branch ? vW : vH;
        const float* gp = g_gap + n * CDIM;
        const float* wr = w + row * CDIM;
        float s = 0.f;
        #pragma unroll
        for (int c = 0; c < CDIM; c++) s += gp[c] * wr[c];
        float f = (s - mm[row]) * (gg[row] * rsqrtf(vv[row] + EPSV)) + bb[row];
        taps[t] = tanhf(f);
    }
    __syncthreads();

    float fh0 = taps[0], fh1 = taps[1], fh2 = taps[2];
    float fw0 = taps[3], fw1 = taps[4], fw2 = taps[5];

    const float4* xp4 = (const float4*)(x + (size_t)plane * HH * WW);
    const float*  xp  = x + (size_t)plane * HH * WW;

    float4* o1 = (float4*)(out + ((size_t)n * 2 * CDIM + cch) * HH * WW);
    float4* o2 = o1 + (size_t)CDIM * HH * WW / 4;

    auto process = [&](int h, const float4& up, const float4& ce, const float4& dn) {
        float xl = (g == 0)  ? ce.y : xp[h * WW + 4 * g - 1];   // reflect left
        float xr = (g == 63) ? ce.z : xp[h * WW + 4 * g + 4];   // reflect right
        float4 h4;
        h4.x = fh0 * xl   + fh1 * ce.x + fh2 * ce.y;
        h4.y = fh0 * ce.x + fh1 * ce.y + fh2 * ce.z;
        h4.z = fh0 * ce.y + fh1 * ce.z + fh2 * ce.w;
        h4.w = fh0 * ce.z + fh1 * ce.w + fh2 * xr;
        float4 v4;
        v4.x = fw0 * up.x + fw1 * ce.x + fw2 * dn.x;
        v4.y = fw0 * up.y + fw1 * ce.y + fw2 * dn.y;
        v4.z = fw0 * up.z + fw1 * ce.z + fw2 * dn.z;
        v4.w = fw0 * up.w + fw1 * ce.w + fw2 * dn.w;
        __stcs(&o1[h * (WW / 4) + g], h4);   // streaming: don't evict x from L2
        __stcs(&o2[h * (WW / 4) + g], v4);
    };

    // rolling window: u = row h-1, cc = row h
    int hu = (h0 == 0) ? 1 : h0 - 1;         // reflect top
    float4 u  = xp4[hu * (WW / 4) + g];
    float4 cc = xp4[h0 * (WW / 4) + g];

    #pragma unroll
    for (int hb = 0; hb < RPT; hb += 4) {
        int h = h0 + hb;
        int r1 = h + 1, r2 = h + 2, r3 = h + 3, r4 = h + 4;
        if (r4 > HH - 1) r4 = HH - 2;        // reflect bottom (only last batch)
        if (r3 > HH - 1) r3 = HH - 2;
        // 4 independent vector loads -> MLP 4
        float4 d0 = xp4[r1 * (WW / 4) + g];
        float4 d1 = xp4[r2 * (WW / 4) + g];
        float4 d2 = xp4[r3 * (WW / 4) + g];
        float4 d3 = xp4[r4 * (WW / 4) + g];

        process(h,     u,  cc, d0);
        process(h + 1, cc, d0, d1);
        process(h + 2, d0, d1, d2);
        process(h + 3, d1, d2, d3);

        u  = d2;
        cc = d3;
    }
}

extern "C" void kernel_launch(void* const* d_in, const int* in_sizes, int n_in,
                              void* d_out, int out_size) {
    const float* x  = (const float*)d_in[0];
    const float* wH = (const float*)d_in[1];
    const float* gH = (const float*)d_in[2];
    const float* bH = (const float*)d_in[3];
    const float* mH = (const float*)d_in[4];
    const float* vH = (const float*)d_in[5];
    const float* wW = (const float*)d_in[6];
    const float* gW = (const float*)d_in[7];
    const float* bW = (const float*)d_in[8];
    const float* mW = (const float*)d_in[9];
    const float* vW = (const float*)d_in[10];
    float* out = (float*)d_out;

    gap_kernel<<<NB * CDIM, 512>>>(x);
    conv_kernel<<<2 * NB * CDIM, 256>>>(x, out, wH, gH, bH, mH, vH,
                                        wW, gW, bW, mW, vW);
}

// round 9
// speedup vs baseline: 1.0837x; 1.0413x over previous
#include <cuda_runtime.h>
#include <cstdint>

#define NB   8
#define CDIM 64
#define HH   256
#define WW   256
#define KK   3
#define EPSV 1e-5f
#define RPT  16   // rows per thread in conv

// scratch (allocation-free rule: device globals)
__device__ float g_gap[NB * CDIM];

// ---------------- Kernel 1: global average pool per (n,c) plane ----------------
__global__ void gap_kernel(const float* __restrict__ x) {
    int nc = blockIdx.x;                 // 0..511
    const float4* p = (const float4*)(x + (size_t)nc * HH * WW);
    float s = 0.f;
    #pragma unroll 8
    for (int i = threadIdx.x; i < (HH * WW) / 4; i += 512) {
        float4 v = p[i];
        s += (v.x + v.y) + (v.z + v.w);
    }
    // warp-level reduce, then one smem round over 16 warp sums
    #pragma unroll
    for (int o = 16; o > 0; o >>= 1)
        s += __shfl_down_sync(0xFFFFFFFFu, s, o);
    __shared__ float red[16];
    if ((threadIdx.x & 31) == 0) red[threadIdx.x >> 5] = s;
    __syncthreads();
    if (threadIdx.x < 32) {
        float t = (threadIdx.x < 16) ? red[threadIdx.x] : 0.f;
        #pragma unroll
        for (int o = 8; o > 0; o >>= 1)
            t += __shfl_down_sync(0xFFFFFFFFu, t, o);
        if (threadIdx.x == 0)
            g_gap[nc] = t * (1.0f / (HH * WW));
    }
}

// ---------------- Kernel 2: fused taps + strip conv ----------------
// grid = 2048 blocks (4 per (n,c) plane: quarter = 64 rows each), 256 threads.
// thread: g = t&63 (float4 column group), chunk = t>>6 (4 chunks of RPT=16 rows).
// Block prologue: threads 0..5 compute the 6 dynamic taps (BN+tanh over the
// gap-GEMV row) and broadcast via smem.
__global__ void __launch_bounds__(256, 6) conv_kernel(
        const float* __restrict__ x, float* __restrict__ out,
        const float* __restrict__ wH, const float* __restrict__ gH,
        const float* __restrict__ bH, const float* __restrict__ mH,
        const float* __restrict__ vH,
        const float* __restrict__ wW, const float* __restrict__ gW,
        const float* __restrict__ bW, const float* __restrict__ mW,
        const float* __restrict__ vW) {
    int plane = blockIdx.x >> 2;         // nc, 0..511
    int quart = blockIdx.x & 3;
    int n   = plane >> 6;
    int cch = plane & 63;
    int t = threadIdx.x;
    int g = t & 63;
    int h0 = quart * 64 + (t >> 6) * RPT;

    __shared__ float taps[6];            // [0..2]=H, [3..5]=W
    if (t < 6) {
        int branch = t / 3;              // 0=H, 1=W
        int k = t - branch * 3;
        int row = cch * 3 + k;
        const float* w = branch ? wW : wH;
        const float* gg = branch ? gW : gH;
        const float* bb = branch ? bW : bH;
        const float* mm = branch ? mW : mH;
        const float* vv = branch ? vW : vH;
        const float* gp = g_gap + n * CDIM;
        const float* wr = w + row * CDIM;
        float s = 0.f;
        #pragma unroll
        for (int c = 0; c < CDIM; c++) s += gp[c] * wr[c];
        float f = (s - mm[row]) * (gg[row] * rsqrtf(vv[row] + EPSV)) + bb[row];
        taps[t] = tanhf(f);
    }
    __syncthreads();

    float fh0 = taps[0], fh1 = taps[1], fh2 = taps[2];
    float fw0 = taps[3], fw1 = taps[4], fw2 = taps[5];

    const float4* xp4 = (const float4*)(x + (size_t)plane * HH * WW);
    const float*  xp  = x + (size_t)plane * HH * WW;

    float4* o1 = (float4*)(out + ((size_t)n * 2 * CDIM + cch) * HH * WW);
    float4* o2 = o1 + (size_t)CDIM * HH * WW / 4;

    auto process = [&](int h, const float4& up, const float4& ce, const float4& dn) {
        float xl = (g == 0)  ? ce.y : xp[h * WW + 4 * g - 1];   // reflect left
        float xr = (g == 63) ? ce.z : xp[h * WW + 4 * g + 4];   // reflect right
        float4 h4;
        h4.x = fh0 * xl   + fh1 * ce.x + fh2 * ce.y;
        h4.y = fh0 * ce.x + fh1 * ce.y + fh2 * ce.z;
        h4.z = fh0 * ce.y + fh1 * ce.z + fh2 * ce.w;
        h4.w = fh0 * ce.z + fh1 * ce.w + fh2 * xr;
        float4 v4;
        v4.x = fw0 * up.x + fw1 * ce.x + fw2 * dn.x;
        v4.y = fw0 * up.y + fw1 * ce.y + fw2 * dn.y;
        v4.z = fw0 * up.z + fw1 * ce.z + fw2 * dn.z;
        v4.w = fw0 * up.w + fw1 * ce.w + fw2 * dn.w;
        __stcs(&o1[h * (WW / 4) + g], h4);   // streaming: don't evict x from L2
        __stcs(&o2[h * (WW / 4) + g], v4);
    };

    // rolling window: u = row h-1, cc = row h
    int hu = (h0 == 0) ? 1 : h0 - 1;         // reflect top
    float4 u  = xp4[hu * (WW / 4) + g];
    float4 cc = xp4[h0 * (WW / 4) + g];

    #pragma unroll
    for (int hb = 0; hb < RPT; hb += 4) {
        int h = h0 + hb;
        int r1 = h + 1, r2 = h + 2, r3 = h + 3, r4 = h + 4;
        if (r4 > HH - 1) r4 = HH - 2;        // reflect bottom (only last batch)
        if (r3 > HH - 1) r3 = HH - 2;
        // 4 independent vector loads -> MLP 4
        float4 d0 = xp4[r1 * (WW / 4) + g];
        float4 d1 = xp4[r2 * (WW / 4) + g];
        float4 d2 = xp4[r3 * (WW / 4) + g];
        float4 d3 = xp4[r4 * (WW / 4) + g];

        process(h,     u,  cc, d0);
        process(h + 1, cc, d0, d1);
        process(h + 2, d0, d1, d2);
        process(h + 3, d1, d2, d3);

        u  = d2;
        cc = d3;
    }
}

extern "C" void kernel_launch(void* const* d_in, const int* in_sizes, int n_in,
                              void* d_out, int out_size) {
    const float* x  = (const float*)d_in[0];
    const float* wH = (const float*)d_in[1];
    const float* gH = (const float*)d_in[2];
    const float* bH = (const float*)d_in[3];
    const float* mH = (const float*)d_in[4];
    const float* vH = (const float*)d_in[5];
    const float* wW = (const float*)d_in[6];
    const float* gW = (const float*)d_in[7];
    const float* bW = (const float*)d_in[8];
    const float* mW = (const float*)d_in[9];
    const float* vW = (const float*)d_in[10];
    float* out = (float*)d_out;

    gap_kernel<<<NB * CDIM, 512>>>(x);
    conv_kernel<<<4 * NB * CDIM, 256>>>(x, out, wH, gH, bH, mH, vH,
                                        wW, gW, bW, mW, vW);
}

// round 10
// speedup vs baseline: 1.1300x; 1.0427x over previous
#include <cuda_runtime.h>
#include <cstdint>

#define NB   8
#define CDIM 64
#define HH   256
#define WW   256
#define KK   3
#define EPSV 1e-5f
#define RPT  16   // rows per thread in conv

// scratch (allocation-free rule: device globals)
__device__ float g_gap[NB * CDIM];

// ---------------- Kernel 1: global average pool per (n,c) plane ----------------
__global__ void gap_kernel(const float* __restrict__ x) {
    int nc = blockIdx.x;                 // 0..511
    const float4* p = (const float4*)(x + (size_t)nc * HH * WW);
    float s = 0.f;
    #pragma unroll 8
    for (int i = threadIdx.x; i < (HH * WW) / 4; i += 512) {
        float4 v = p[i];
        s += (v.x + v.y) + (v.z + v.w);
    }
    // warp-level reduce, then one smem round over 16 warp sums
    #pragma unroll
    for (int o = 16; o > 0; o >>= 1)
        s += __shfl_down_sync(0xFFFFFFFFu, s, o);
    __shared__ float red[16];
    if ((threadIdx.x & 31) == 0) red[threadIdx.x >> 5] = s;
    __syncthreads();
    if (threadIdx.x < 32) {
        float t = (threadIdx.x < 16) ? red[threadIdx.x] : 0.f;
        #pragma unroll
        for (int o = 8; o > 0; o >>= 1)
            t += __shfl_down_sync(0xFFFFFFFFu, t, o);
        if (threadIdx.x == 0)
            g_gap[nc] = t * (1.0f / (HH * WW));
    }
}

// ---------------- Kernel 2: fused taps + strip conv ----------------
// grid = 2048 blocks (4 per (n,c) plane), 256 threads.
// Planes processed in REVERSE order vs gap_kernel so conv's reads hit the
// x data gap most recently left in L2 (forward rescan would chase the LRU
// eviction front and miss everywhere; reverse rescan stays behind it).
__global__ void __launch_bounds__(256, 6) conv_kernel(
        const float* __restrict__ x, float* __restrict__ out,
        const float* __restrict__ wH, const float* __restrict__ gH,
        const float* __restrict__ bH, const float* __restrict__ mH,
        const float* __restrict__ vH,
        const float* __restrict__ wW, const float* __restrict__ gW,
        const float* __restrict__ bW, const float* __restrict__ mW,
        const float* __restrict__ vW) {
    int plane = (NB * CDIM - 1) - (blockIdx.x >> 2);   // 511..0 (reverse)
    int quart = blockIdx.x & 3;
    int n   = plane >> 6;
    int cch = plane & 63;
    int t = threadIdx.x;
    int g = t & 63;
    int h0 = quart * 64 + (t >> 6) * RPT;

    __shared__ float taps[6];            // [0..2]=H, [3..5]=W
    if (t < 6) {
        int branch = t / 3;              // 0=H, 1=W
        int k = t - branch * 3;
        int row = cch * 3 + k;
        const float* w = branch ? wW : wH;
        const float* gg = branch ? gW : gH;
        const float* bb = branch ? bW : bH;
        const float* mm = branch ? mW : mH;
        const float* vv = branch ? vW : vH;
        const float* gp = g_gap + n * CDIM;
        const float* wr = w + row * CDIM;
        float s = 0.f;
        #pragma unroll
        for (int c = 0; c < CDIM; c++) s += gp[c] * wr[c];
        float f = (s - mm[row]) * (gg[row] * rsqrtf(vv[row] + EPSV)) + bb[row];
        taps[t] = tanhf(f);
    }
    __syncthreads();

    float fh0 = taps[0], fh1 = taps[1], fh2 = taps[2];
    float fw0 = taps[3], fw1 = taps[4], fw2 = taps[5];

    const float4* xp4 = (const float4*)(x + (size_t)plane * HH * WW);
    const float*  xp  = x + (size_t)plane * HH * WW;

    float4* o1 = (float4*)(out + ((size_t)n * 2 * CDIM + cch) * HH * WW);
    float4* o2 = o1 + (size_t)CDIM * HH * WW / 4;

    auto process = [&](int h, const float4& up, const float4& ce, const float4& dn) {
        float xl = (g == 0)  ? ce.y : xp[h * WW + 4 * g - 1];   // reflect left
        float xr = (g == 63) ? ce.z : xp[h * WW + 4 * g + 4];   // reflect right
        float4 h4;
        h4.x = fh0 * xl   + fh1 * ce.x + fh2 * ce.y;
        h4.y = fh0 * ce.x + fh1 * ce.y + fh2 * ce.z;
        h4.z = fh0 * ce.y + fh1 * ce.z + fh2 * ce.w;
        h4.w = fh0 * ce.z + fh1 * ce.w + fh2 * xr;
        float4 v4;
        v4.x = fw0 * up.x + fw1 * ce.x + fw2 * dn.x;
        v4.y = fw0 * up.y + fw1 * ce.y + fw2 * dn.y;
        v4.z = fw0 * up.z + fw1 * ce.z + fw2 * dn.z;
        v4.w = fw0 * up.w + fw1 * ce.w + fw2 * dn.w;
        __stcs(&o1[h * (WW / 4) + g], h4);   // streaming: don't evict x from L2
        __stcs(&o2[h * (WW / 4) + g], v4);
    };

    // rolling window: u = row h-1, cc = row h
    int hu = (h0 == 0) ? 1 : h0 - 1;         // reflect top
    float4 u  = xp4[hu * (WW / 4) + g];
    float4 cc = xp4[h0 * (WW / 4) + g];

    #pragma unroll
    for (int hb = 0; hb < RPT; hb += 4) {
        int h = h0 + hb;
        int r1 = h + 1, r2 = h + 2, r3 = h + 3, r4 = h + 4;
        if (r4 > HH - 1) r4 = HH - 2;        // reflect bottom (only last batch)
        if (r3 > HH - 1) r3 = HH - 2;
        // 4 independent vector loads -> MLP 4
        float4 d0 = xp4[r1 * (WW / 4) + g];
        float4 d1 = xp4[r2 * (WW / 4) + g];
        float4 d2 = xp4[r3 * (WW / 4) + g];
        float4 d3 = xp4[r4 * (WW / 4) + g];

        process(h,     u,  cc, d0);
        process(h + 1, cc, d0, d1);
        process(h + 2, d0, d1, d2);
        process(h + 3, d1, d2, d3);

        u  = d2;
        cc = d3;
    }
}

extern "C" void kernel_launch(void* const* d_in, const int* in_sizes, int n_in,
                              void* d_out, int out_size) {
    const float* x  = (const float*)d_in[0];
    const float* wH = (const float*)d_in[1];
    const float* gH = (const float*)d_in[2];
    const float* bH = (const float*)d_in[3];
    const float* mH = (const float*)d_in[4];
    const float* vH = (const float*)d_in[5];
    const float* wW = (const float*)d_in[6];
    const float* gW = (const float*)d_in[7];
    const float* bW = (const float*)d_in[8];
    const float* mW = (const float*)d_in[9];
    const float* vW = (const float*)d_in[10];
    float* out = (float*)d_out;

    gap_kernel<<<NB * CDIM, 512>>>(x);
    conv_kernel<<<4 * NB * CDIM, 256>>>(x, out, wH, gH, bH, mH, vH,
                                        wW, gW, bW, mW, vW);
}